// round 14
// baseline (speedup 1.0000x reference)
#include <cuda_runtime.h>
#include <cuda_bf16.h>
#include <cuda_fp16.h>
#include <math.h>
#include <stdint.h>

#define Tt 8192
#define Kk 64
#define NBLK 512            // pipeline blocks
#define TPB 128             // timesteps per block
#define SEQB 64             // pipeline blocks per sequence
#define NTH 256

// dynamic smem byte offsets (pipeline blocks)
// phase 1: xhi[128][136]h =34816 | xlo =34816 | whi[64][136]h =17408 | wlo =17408
#define XHI_B 0u
#define XLO_B 34816u
#define WHI_B 69632u
#define WLO_B 87040u
#define SMEM_BYTES 104448
// phase 2 (reuse): sU f32[128][68] @0 | adth u32[128][68] @34816 | cum u32[128][68] @69632

// ---- device scratch (static; no runtime alloc allowed) ----
// Monotone generation counters: each block takes L = ++g_gen[bid] on entry;
// publishes bump counters to L; waiters spin until >= L. Exactly-once per
// execution keeps graph replays in lockstep with NO reset kernel.
__device__ float4 g_agg[NBLK*Kk];      // per-block aggregate (Ar,Ai,Zr,Zi), [lin][k]
__device__ int    g_gen[NBLK+1];       // per-block entry counters
__device__ int    g_bst[NBLK];         // aggregate-published counters
__device__ int    g_sflag;             // sigma-published counter
__device__ float  g_sigma_inv;

__device__ __forceinline__ float softplusf(float x){
    return (x > 20.f) ? x : log1pf(expf(x));
}
__device__ __forceinline__ uint32_t smem_u32(const void* p){
    uint32_t a;
    asm("{ .reg .u64 t; cvta.to.shared.u64 t, %1; cvt.u32.u64 %0, t; }" : "=r"(a) : "l"(p));
    return a;
}
__device__ __forceinline__ uint32_t pack_bf2(float lo, float hi){
    uint32_t r;
    asm("cvt.rn.bf16x2.f32 %0, %1, %2;" : "=r"(r) : "f"(hi), "f"(lo));
    return r;
}
#define LDSM_X4(r0,r1,r2,r3,addr) \
    asm volatile("ldmatrix.sync.aligned.m8n8.x4.shared.b16 {%0,%1,%2,%3}, [%4];" \
        : "=r"(r0),"=r"(r1),"=r"(r2),"=r"(r3) : "r"(addr))
#define MMA_BF16(c0,c1,c2,c3,a0,a1,a2,a3,b0,b1) \
    asm volatile("mma.sync.aligned.m16n8k16.row.col.f32.bf16.bf16.f32 " \
        "{%0,%1,%2,%3},{%4,%5,%6,%7},{%8,%9},{%0,%1,%2,%3};" \
        : "+f"(c0),"+f"(c1),"+f"(c2),"+f"(c3) \
        : "r"(a0),"r"(a1),"r"(a2),"r"(a3),"r"(b0),"r"(b1))

// ============================ fused kernel ==================================
__global__ void __launch_bounds__(NTH, 2)
k_fused(const float* __restrict__ x,
        const float* __restrict__ dt,
        const float* __restrict__ alpha_mod,
        const float* __restrict__ omega_mod,
        const float* __restrict__ tau_mod,
        const float* __restrict__ bvec,
        const float* __restrict__ W,
        const float* __restrict__ s_real_raw,
        const float* __restrict__ s_imag,
        const float* __restrict__ tau_raw,
        float* __restrict__ out)
{
    extern __shared__ float sm[];
    int tid = threadIdx.x;   // 256

    if (blockIdx.x == 0) {
        // ------------------------- sigma block ------------------------------
        float* sW = sm;               // 64 x 132
        float* M  = sm + 64*132;      // 64 x 68
        float* H  = sm + 64*132 + 64*68;
        __shared__ float vbuf[2][64];
        __shared__ float red[64];
        __shared__ float red2[64];

        const float4* W4 = (const float4*)W;
        #pragma unroll
        for (int r = 0; r < 8; ++r) {
            int lin = tid + r*256;
            int k = lin >> 5, d4 = lin & 31;
            ((float4*)&sW[k*132])[d4] = W4[lin];
        }
        __syncthreads();

        int ti = tid >> 4, tj = tid & 15;
        {   // Gram: M = W W^T
            float acc[4][4];
            #pragma unroll
            for (int a=0;a<4;a++){
                #pragma unroll
                for (int b2=0;b2<4;b2++) acc[a][b2]=0.f;
            }
            #pragma unroll 4
            for (int d4 = 0; d4 < 32; ++d4) {
                float4 av[4], bv[4];
                #pragma unroll
                for (int a=0;a<4;a++)  av[a] = ((const float4*)&sW[(ti*4+a)*132])[d4];
                #pragma unroll
                for (int b2=0;b2<4;b2++) bv[b2] = ((const float4*)&sW[(tj*4+b2)*132])[d4];
                #pragma unroll
                for (int a=0;a<4;a++){
                    #pragma unroll
                    for (int b2=0;b2<4;b2++){
                        acc[a][b2] += av[a].x*bv[b2].x + av[a].y*bv[b2].y
                                    + av[a].z*bv[b2].z + av[a].w*bv[b2].w;
                    }
                }
            }
            #pragma unroll
            for (int a=0;a<4;a++){
                #pragma unroll
                for (int b2=0;b2<4;b2++)
                    M[(ti*4+a)*68 + (tj*4+b2)] = acc[a][b2];
            }
        }
        __syncthreads();

        float* cur = M; float* oth = H;
        for (int sq = 0; sq < 5; ++sq) {     // G^32 (trace-normalized)
            float acc[4][4];
            #pragma unroll
            for (int a=0;a<4;a++){
                #pragma unroll
                for (int b2=0;b2<4;b2++) acc[a][b2]=0.f;
            }
            #pragma unroll 4
            for (int l = 0; l < 64; ++l) {
                float a0 = cur[(ti*4+0)*68 + l];
                float a1 = cur[(ti*4+1)*68 + l];
                float a2 = cur[(ti*4+2)*68 + l];
                float a3 = cur[(ti*4+3)*68 + l];
                float4 bv = *(const float4*)&cur[l*68 + tj*4];
                acc[0][0]+=a0*bv.x; acc[0][1]+=a0*bv.y; acc[0][2]+=a0*bv.z; acc[0][3]+=a0*bv.w;
                acc[1][0]+=a1*bv.x; acc[1][1]+=a1*bv.y; acc[1][2]+=a1*bv.z; acc[1][3]+=a1*bv.w;
                acc[2][0]+=a2*bv.x; acc[2][1]+=a2*bv.y; acc[2][2]+=a2*bv.z; acc[2][3]+=a2*bv.w;
                acc[3][0]+=a3*bv.x; acc[3][1]+=a3*bv.y; acc[3][2]+=a3*bv.z; acc[3][3]+=a3*bv.w;
            }
            #pragma unroll
            for (int a=0;a<4;a++){
                #pragma unroll
                for (int b2=0;b2<4;b2++)
                    oth[(ti*4+a)*68 + tj*4+b2] = acc[a][b2];
            }
            __syncthreads();
            if (tid < 64) red[tid] = oth[tid*68 + tid];
            __syncthreads();
            for (int s = 32; s > 0; s >>= 1) {
                if (tid < s) red[tid] += red[tid+s];
                __syncthreads();
            }
            float sc = 1.0f / red[0];
            #pragma unroll
            for (int r = 0; r < 16; ++r) {
                int lin = tid + r*256;
                oth[(lin>>6)*68 + (lin&63)] *= sc;
            }
            __syncthreads();
            float* t = cur; cur = oth; oth = t;
        }
        if (tid < 64) vbuf[0][tid] = 1.0f + 0.001f*(float)tid;
        __syncthreads();
        int i = tid >> 2, p4 = tid & 3;
        for (int it = 0; it < 6; ++it) {
            const float* v = vbuf[it & 1];
            float s = 0.f;
            #pragma unroll
            for (int l4 = 0; l4 < 4; ++l4) {
                int lb = p4*16 + l4*4;
                float4 m = *(const float4*)&cur[i*68 + lb];
                s += m.x*v[lb] + m.y*v[lb+1] + m.z*v[lb+2] + m.w*v[lb+3];
            }
            s += __shfl_xor_sync(0xffffffffu, s, 1);
            s += __shfl_xor_sync(0xffffffffu, s, 2);
            if (p4 == 0) vbuf[(it+1)&1][i] = s;
            __syncthreads();
            if (it == 3) {
                float* vn = vbuf[(it+1)&1];
                if (tid < 64) red[tid] = vn[tid]*vn[tid];
                __syncthreads();
                for (int st = 32; st > 0; st >>= 1) {
                    if (tid < st) red[tid] += red[tid+st];
                    __syncthreads();
                }
                float scl = rsqrtf(red[0]);
                if (tid < 64) vn[tid] *= scl;
                __syncthreads();
            }
        }
        const float* vf = vbuf[0];
        float* tvec = oth;
        if (tid < 128) {
            float s = 0.f;
            #pragma unroll 4
            for (int kk = 0; kk < 64; ++kk) s += sW[kk*132 + tid] * vf[kk];
            tvec[tid] = s;
        }
        __syncthreads();
        if (tid < 64) {
            float s = 0.f;
            #pragma unroll 4
            for (int d = 0; d < 128; ++d) s += sW[tid*132 + d] * tvec[d];
            red[tid]  = s * vf[tid];
            red2[tid] = vf[tid]*vf[tid];
        }
        __syncthreads();
        for (int st = 32; st > 0; st >>= 1) {
            if (tid < st) { red[tid] += red[tid+st]; red2[tid] += red2[tid+st]; }
            __syncthreads();
        }
        if (tid == 0) {
            g_sigma_inv = rsqrtf(red[0] / red2[0]);
            __threadfence();
            atomicAdd(&g_sflag, 1);
        }
        return;
    }

    // ------------------------- pipeline blocks ------------------------------
    __shared__ float4 sSum[4*64];
    __shared__ float2 sPre[64];
    __shared__ float  sA0[64];
    __shared__ float  sO0[64];
    __shared__ int    sL;

    int lin = blockIdx.x - 1;         // 0..511
    int p   = lin & (SEQB-1);
    int bt0 = lin * TPB;
    int lane = tid & 31, wid = tid >> 5;

    if (tid == 0) sL = atomicAdd(&g_gen[blockIdx.x], 1) + 1;

    // --- convert x/W -> bf16 hi/lo planes ---
    char* smc = (char*)sm;
    uint32_t* xhi = (uint32_t*)(smc + XHI_B);   // u32 index = row*68 + d2
    uint32_t* xlo = (uint32_t*)(smc + XLO_B);
    uint32_t* whi = (uint32_t*)(smc + WHI_B);
    uint32_t* wlo = (uint32_t*)(smc + WLO_B);

    const float4* xg4 = (const float4*)x + (size_t)bt0*32;
    #pragma unroll
    for (int r = 0; r < 16; ++r) {
        int l = tid + r*256;
        int row = l >> 5, d4 = l & 31;
        float4 v = xg4[l];
        __nv_bfloat16 hx = __float2bfloat16_rn(v.x), hy = __float2bfloat16_rn(v.y);
        __nv_bfloat16 hz = __float2bfloat16_rn(v.z), hw = __float2bfloat16_rn(v.w);
        uint2 hiq, loq;
        {
            __nv_bfloat162 p0; p0.x = hx; p0.y = hy; hiq.x = *(uint32_t*)&p0;
            __nv_bfloat162 p1; p1.x = hz; p1.y = hw; hiq.y = *(uint32_t*)&p1;
        }
        loq.x = pack_bf2(v.x - __bfloat162float(hx), v.y - __bfloat162float(hy));
        loq.y = pack_bf2(v.z - __bfloat162float(hz), v.w - __bfloat162float(hw));
        *(uint2*)&xhi[row*68 + d4*2] = hiq;
        *(uint2*)&xlo[row*68 + d4*2] = loq;
    }
    const float4* Wg4 = (const float4*)W;
    #pragma unroll
    for (int r = 0; r < 8; ++r) {
        int l = tid + r*256;
        int row = l >> 5, d4 = l & 31;
        float4 v = Wg4[l];
        __nv_bfloat16 hx = __float2bfloat16_rn(v.x), hy = __float2bfloat16_rn(v.y);
        __nv_bfloat16 hz = __float2bfloat16_rn(v.z), hw = __float2bfloat16_rn(v.w);
        uint2 hiq, loq;
        {
            __nv_bfloat162 p0; p0.x = hx; p0.y = hy; hiq.x = *(uint32_t*)&p0;
            __nv_bfloat162 p1; p1.x = hz; p1.y = hw; hiq.y = *(uint32_t*)&p1;
        }
        loq.x = pack_bf2(v.x - __bfloat162float(hx), v.y - __bfloat162float(hy));
        loq.y = pack_bf2(v.z - __bfloat162float(hz), v.w - __bfloat162float(hw));
        *(uint2*)&whi[row*68 + d4*2] = hiq;
        *(uint2*)&wlo[row*68 + d4*2] = loq;
    }
    if (tid < 64) {
        float tauv = softplusf(tau_raw[0]) + 1e-3f;
        sA0[tid] = (softplusf(s_real_raw[tid]) + 1e-6f) * tauv;
        sO0[tid] = s_imag[tid] * tauv;
    }
    __syncthreads();
    int L = sL;

    // --- HMMA GEMM: warp w = rows [w*16, w*16+16), all 64 k, K=128 ---
    uint32_t smb = smem_u32(sm);
    uint32_t aoff = (uint32_t)(((wid*16 + (lane & 15))*136 + (lane >> 4)*8) * 2);
    uint32_t boff = (uint32_t)(((((lane & 7) + ((lane >> 3) & 1)*8))*136 + (lane >> 4)*8) * 2);

    float c[8][4];
    #pragma unroll
    for (int nt = 0; nt < 8; ++nt){
        #pragma unroll
        for (int q = 0; q < 4; ++q) c[nt][q] = 0.f;
    }
    const uint32_t Ab[3] = {XHI_B, XHI_B, XLO_B};
    const uint32_t Bb[3] = {WHI_B, WLO_B, WHI_B};
    #pragma unroll
    for (int ps = 0; ps < 3; ++ps) {
        uint32_t Abase = smb + Ab[ps] + aoff;
        uint32_t Bbase = smb + Bb[ps] + boff;
        #pragma unroll
        for (int ks = 0; ks < 8; ++ks) {
            uint32_t a0,a1,a2,a3;
            LDSM_X4(a0,a1,a2,a3, Abase + ks*32);
            #pragma unroll
            for (int np = 0; np < 4; ++np) {
                uint32_t b0,b1,b2,b3;
                LDSM_X4(b0,b1,b2,b3, Bbase + np*4352 + ks*32);
                MMA_BF16(c[np*2][0],c[np*2][1],c[np*2][2],c[np*2][3],
                         a0,a1,a2,a3, b0,b2);
                MMA_BF16(c[np*2+1][0],c[np*2+1][1],c[np*2+1][2],c[np*2+1][3],
                         a0,a1,a2,a3, b1,b3);
            }
        }
    }
    __syncthreads();   // tiles dead; reuse as staging

    float*    sU   = sm;                          // [128][68] f32 (u, then z_r)
    uint32_t* adth = (uint32_t*)(smc + 34816);    // [128][68] half2(ad,th), then z_i
    uint32_t* cum  = (uint32_t*)(smc + 69632);    // [128][68] half2(sum_ad, sum_th)

    // --- store D fragments -> sU ---
    {
        int g = wid*16 + (lane >> 2);
        int cb = 2*(lane & 3);
        #pragma unroll
        for (int nt = 0; nt < 8; ++nt) {
            int col = nt*8 + cb;
            *(float2*)&sU[g*68 + col]     = make_float2(c[nt][0], c[nt][1]);
            *(float2*)&sU[(g+8)*68 + col] = make_float2(c[nt][2], c[nt][3]);
        }
    }

    // --- epilogue: (ad,th) -> half2 ---
    int kq = tid & 7, bq = tid >> 3;
    #pragma unroll
    for (int a = 0; a < 4; ++a) {
        int tl = bq*4 + a;
        int bt = bt0 + tl;
        float dtv = dt[bt];
        float tm  = tau_mod[bt];
        #pragma unroll
        for (int j = 0; j < 8; ++j) {
            int k2 = kq + 8*j;
            int idx = bt*64 + k2;
            float ad = sA0[k2] * __expf(alpha_mod[idx] + tm) * dtv;
            float th = sO0[k2] * __expf(omega_mod[idx] + tm) * dtv;
            __half2 hv = __floats2half2_rn(ad, th);
            adth[tl*68 + k2] = *(uint32_t*)&hv;
        }
    }

    // --- wait for sigma (overlapped by GEMM + epilogue) ---
    if (tid == 0) {
        while (atomicAdd(&g_sflag, 0) < L) __nanosleep(100);
    }
    __syncthreads();
    __threadfence();
    float siginv = *(volatile float*)&g_sigma_inv;

    int cc = tid >> 6, k = tid & 63;  // 4 sub-chunks x 64 lanes
    float bk = bvec[k];

    // --- pass 1: local sub-chunk scans; store z_local + cumulative (ad,th)
    //     in place. Makes pass 2 embarrassingly parallel. ---
    {
        int tb = cc*32;
        float zr=0.f, zi=0.f, sad=0.f, sth=0.f;
        #pragma unroll 8
        for (int i = 0; i < 32; ++i) {
            int idx = (tb+i)*68 + k;
            uint32_t pk = adth[idx];
            float2 at = __half22float2(*(__half2*)&pk);
            float u  = siginv*sU[idx] + bk;
            float ad = at.x, th = at.y;
            float rho = 1.f - ad*(1.f - ad*(0.5f - 0.16666667f*ad));
            float t2  = th*th;
            float cs  = 1.f - 0.5f*t2*(1.f - 0.083333336f*t2);
            float sn  = th*(1.f - 0.16666667f*t2);
            float ar = rho*cs, ai = rho*sn;
            float nr = ar*zr - ai*zi + u;
            float ni = ai*zr + ar*zi;
            zr = nr; zi = ni;
            sad += ad; sth += th;
            sU[idx]   = zr;                    // z_local real (u consumed)
            adth[idx] = __float_as_uint(zi);   // z_local imag (ad/th consumed)
            __half2 hc = __floats2half2_rn(sad, sth);
            cum[idx]  = *(uint32_t*)&hc;       // cumulative decay/phase
        }
        // sub-chunk multiplier from cumulative sums (same Taylor family;
        // sums <= ~0.08 so truncation ~1e-6)
        float rho = 1.f - sad*(1.f - sad*(0.5f - 0.16666667f*sad));
        float t2  = sth*sth;
        float cs  = 1.f - 0.5f*t2*(1.f - 0.083333336f*t2);
        float sn  = sth*(1.f - 0.16666667f*t2);
        sSum[cc*64 + k] = make_float4(rho*cs, rho*sn, zr, zi);
    }
    __syncthreads();

    // --- block aggregate (lanes 0..63), publish agg + counter ---
    if (tid < 64) {
        float bAr=1.f, bAi=0.f, bZr=0.f, bZi=0.f;
        #pragma unroll
        for (int j = 0; j < 4; ++j) {
            float4 s4 = sSum[j*64 + tid];
            float nzr = s4.x*bZr - s4.y*bZi + s4.z;
            float nzi = s4.y*bZr + s4.x*bZi + s4.w;
            float nar = s4.x*bAr - s4.y*bAi;
            float nai = s4.y*bAr + s4.x*bAi;
            bZr=nzr; bZi=nzi; bAr=nar; bAi=nai;
        }
        g_agg[lin*Kk + tid] = make_float4(bAr, bAi, bZr, bZi);
        __threadfence();
    }
    __syncthreads();
    if (tid == 0) atomicAdd(&g_bst[lin], 1);

    // --- parallel lookback ---
    float pr = 0.f, pi = 0.f;
    if (p > 0) {
        if (tid < p) {
            while (atomicAdd(&g_bst[lin - 1 - tid], 0) < L) __nanosleep(60);
        }
        __syncthreads();
        __threadfence();
        if (tid < 64) {
            float Ra=1.f, Rb=0.f, Rzr=0.f, Rzi=0.f;
            int w = lin - 1;
            int wend = lin - p;
            while (w >= wend) {
                int nb = w - wend + 1; if (nb > 8) nb = 8;
                float4 ag[8];
                #pragma unroll
                for (int b = 0; b < 8; ++b) {
                    if (b < nb) ag[b] = __ldcg(&g_agg[(w - b)*Kk + tid]);
                }
                #pragma unroll
                for (int b = 0; b < 8; ++b) {
                    if (b < nb) {
                        float4 A = ag[b];
                        float nzr = Ra*A.z - Rb*A.w + Rzr;
                        float nzi = Rb*A.z + Ra*A.w + Rzi;
                        float nar = Ra*A.x - Rb*A.y;
                        float nai = Ra*A.y + Rb*A.x;
                        Rzr=nzr; Rzi=nzi; Ra=nar; Rb=nai;
                    }
                }
                w -= nb;
            }
            pr = Rzr; pi = Rzi;
        }
    }

    if (tid < 64) sPre[tid] = make_float2(pr, pi);
    __syncthreads();

    // --- pass 2: FULLY PARALLEL output: z_t = A_cum(t) x z_in + z_local(t) ---
    {
        float2 z0 = sPre[k];
        float zr0 = z0.x, zi0 = z0.y;
        #pragma unroll
        for (int j = 0; j < 3; ++j) {
            if (j < cc) {
                float4 s4 = sSum[j*64 + k];
                float nr = s4.x*zr0 - s4.y*zi0 + s4.z;
                float ni = s4.y*zr0 + s4.x*zi0 + s4.w;
                zr0 = nr; zi0 = ni;
            }
        }
        int tb = cc*32;
        float* outb = out + (size_t)(bt0 + tb)*128;
        #pragma unroll 8
        for (int i = 0; i < 32; ++i) {
            int idx = (tb+i)*68 + k;
            uint32_t pc = cum[idx];
            float2 st = __half22float2(*(__half2*)&pc);
            float zlr = sU[idx];
            float zli = __uint_as_float(adth[idx]);
            float sad = st.x, sth = st.y;
            float rho = 1.f - sad*(1.f - sad*(0.5f - 0.16666667f*sad));
            float t2  = sth*sth;
            float cs  = 1.f - 0.5f*t2*(1.f - 0.083333336f*t2);
            float sn  = sth*(1.f - 0.16666667f*t2);
            float ar = rho*cs, ai = rho*sn;
            outb[i*128 + k]      = ar*zr0 - ai*zi0 + zlr;   // C
            outb[i*128 + 64 + k] = ai*zr0 + ar*zi0 + zli;   // S
        }
    }
}

extern "C" void kernel_launch(void* const* d_in, const int* in_sizes, int n_in,
                              void* d_out, int out_size)
{
    const float* x          = (const float*)d_in[0];
    const float* dt         = (const float*)d_in[1];
    const float* alpha_mod  = (const float*)d_in[2];
    const float* omega_mod  = (const float*)d_in[3];
    const float* tau_mod    = (const float*)d_in[4];
    const float* s_real_raw = (const float*)d_in[5];
    const float* s_imag     = (const float*)d_in[6];
    const float* tau_raw    = (const float*)d_in[7];
    const float* W          = (const float*)d_in[8];
    const float* bvec       = (const float*)d_in[9];
    float* out = (float*)d_out;

    cudaFuncSetAttribute(k_fused, cudaFuncAttributeMaxDynamicSharedMemorySize, SMEM_BYTES);

    k_fused<<<NBLK + 1, NTH, SMEM_BYTES>>>(x, dt, alpha_mod, omega_mod, tau_mod,
                                           bvec, W, s_real_raw, s_imag, tau_raw, out);
}

// round 15
// speedup vs baseline: 1.0290x; 1.0290x over previous
#include <cuda_runtime.h>
#include <cuda_bf16.h>
#include <cuda_fp16.h>
#include <math.h>
#include <stdint.h>

#define Tt 8192
#define Kk 64
#define NBLK 512            // pipeline blocks
#define TPB 128             // timesteps per block
#define SEQB 64             // pipeline blocks per sequence
#define NTH 256

// dynamic smem byte offsets (pipeline blocks)
// phase 1: xhi[128][136]h =34816 | xlo =34816 | whi[64][136]h =17408 | wlo =17408
#define XHI_B 0u
#define XLO_B 34816u
#define WHI_B 69632u
#define WLO_B 87040u
#define SMEM_BYTES 104448
// phase 2 (reuse): sU f32[128][68] @0 (34816B), adth u32[128][68] @34816

// ---- device scratch (static; no runtime alloc allowed) ----
// Monotone generation counters: each block takes L = ++g_gen[bid] on entry;
// publishes bump counters to L; waiters spin until >= L. Exactly-once per
// execution keeps graph replays in lockstep with NO reset kernel.
__device__ float4 g_agg[NBLK*Kk];      // per-block aggregate (Ar,Ai,Zr,Zi), [lin][k]
__device__ int    g_gen[NBLK+1];       // per-block entry counters
__device__ int    g_bst[NBLK];         // aggregate-published counters
__device__ int    g_sflag;             // sigma-published counter
__device__ float  g_sigma_inv;

__device__ __forceinline__ float softplusf(float x){
    return (x > 20.f) ? x : log1pf(expf(x));
}
__device__ __forceinline__ uint32_t smem_u32(const void* p){
    uint32_t a;
    asm("{ .reg .u64 t; cvta.to.shared.u64 t, %1; cvt.u32.u64 %0, t; }" : "=r"(a) : "l"(p));
    return a;
}
__device__ __forceinline__ uint32_t pack_bf2(float lo, float hi){
    uint32_t r;
    asm("cvt.rn.bf16x2.f32 %0, %1, %2;" : "=r"(r) : "f"(hi), "f"(lo));
    return r;
}
#define LDSM_X4(r0,r1,r2,r3,addr) \
    asm volatile("ldmatrix.sync.aligned.m8n8.x4.shared.b16 {%0,%1,%2,%3}, [%4];" \
        : "=r"(r0),"=r"(r1),"=r"(r2),"=r"(r3) : "r"(addr))
#define MMA_BF16(c0,c1,c2,c3,a0,a1,a2,a3,b0,b1) \
    asm volatile("mma.sync.aligned.m16n8k16.row.col.f32.bf16.bf16.f32 " \
        "{%0,%1,%2,%3},{%4,%5,%6,%7},{%8,%9},{%0,%1,%2,%3};" \
        : "+f"(c0),"+f"(c1),"+f"(c2),"+f"(c3) \
        : "r"(a0),"r"(a1),"r"(a2),"r"(a3),"r"(b0),"r"(b1))

// ============================ fused kernel ==================================
__global__ void __launch_bounds__(NTH, 2)
k_fused(const float* __restrict__ x,
        const float* __restrict__ dt,
        const float* __restrict__ alpha_mod,
        const float* __restrict__ omega_mod,
        const float* __restrict__ tau_mod,
        const float* __restrict__ bvec,
        const float* __restrict__ W,
        const float* __restrict__ s_real_raw,
        const float* __restrict__ s_imag,
        const float* __restrict__ tau_raw,
        float* __restrict__ out)
{
    extern __shared__ float sm[];
    int tid = threadIdx.x;   // 256

    if (blockIdx.x == 0) {
        // ------------------------- sigma block ------------------------------
        float* sW = sm;               // 64 x 132
        float* M  = sm + 64*132;      // 64 x 68
        float* H  = sm + 64*132 + 64*68;
        __shared__ float vbuf[2][64];
        __shared__ float red[64];
        __shared__ float red2[64];

        const float4* W4 = (const float4*)W;
        #pragma unroll
        for (int r = 0; r < 8; ++r) {
            int lin = tid + r*256;
            int k = lin >> 5, d4 = lin & 31;
            ((float4*)&sW[k*132])[d4] = W4[lin];
        }
        __syncthreads();

        int ti = tid >> 4, tj = tid & 15;
        {   // Gram: M = W W^T
            float acc[4][4];
            #pragma unroll
            for (int a=0;a<4;a++){
                #pragma unroll
                for (int b2=0;b2<4;b2++) acc[a][b2]=0.f;
            }
            #pragma unroll 4
            for (int d4 = 0; d4 < 32; ++d4) {
                float4 av[4], bv[4];
                #pragma unroll
                for (int a=0;a<4;a++)  av[a] = ((const float4*)&sW[(ti*4+a)*132])[d4];
                #pragma unroll
                for (int b2=0;b2<4;b2++) bv[b2] = ((const float4*)&sW[(tj*4+b2)*132])[d4];
                #pragma unroll
                for (int a=0;a<4;a++){
                    #pragma unroll
                    for (int b2=0;b2<4;b2++){
                        acc[a][b2] += av[a].x*bv[b2].x + av[a].y*bv[b2].y
                                    + av[a].z*bv[b2].z + av[a].w*bv[b2].w;
                    }
                }
            }
            #pragma unroll
            for (int a=0;a<4;a++){
                #pragma unroll
                for (int b2=0;b2<4;b2++)
                    M[(ti*4+a)*68 + (tj*4+b2)] = acc[a][b2];
            }
        }
        __syncthreads();

        float* cur = M; float* oth = H;
        for (int sq = 0; sq < 5; ++sq) {     // G^32
            float acc[4][4];
            #pragma unroll
            for (int a=0;a<4;a++){
                #pragma unroll
                for (int b2=0;b2<4;b2++) acc[a][b2]=0.f;
            }
            #pragma unroll 4
            for (int l = 0; l < 64; ++l) {
                float a0 = cur[(ti*4+0)*68 + l];
                float a1 = cur[(ti*4+1)*68 + l];
                float a2 = cur[(ti*4+2)*68 + l];
                float a3 = cur[(ti*4+3)*68 + l];
                float4 bv = *(const float4*)&cur[l*68 + tj*4];
                acc[0][0]+=a0*bv.x; acc[0][1]+=a0*bv.y; acc[0][2]+=a0*bv.z; acc[0][3]+=a0*bv.w;
                acc[1][0]+=a1*bv.x; acc[1][1]+=a1*bv.y; acc[1][2]+=a1*bv.z; acc[1][3]+=a1*bv.w;
                acc[2][0]+=a2*bv.x; acc[2][1]+=a2*bv.y; acc[2][2]+=a2*bv.z; acc[2][3]+=a2*bv.w;
                acc[3][0]+=a3*bv.x; acc[3][1]+=a3*bv.y; acc[3][2]+=a3*bv.z; acc[3][3]+=a3*bv.w;
            }
            #pragma unroll
            for (int a=0;a<4;a++){
                #pragma unroll
                for (int b2=0;b2<4;b2++)
                    oth[(ti*4+a)*68 + tj*4+b2] = acc[a][b2];
            }
            __syncthreads();
            // normalize by M[0][0] (> 0 for PSD): no reduction tree needed;
            // any positive scale works (cancels in the final Rayleigh quotient)
            float sc = 1.0f / oth[0];
            #pragma unroll
            for (int r = 0; r < 16; ++r) {
                int lin = tid + r*256;
                oth[(lin>>6)*68 + (lin&63)] *= sc;
            }
            __syncthreads();
            float* t = cur; cur = oth; oth = t;
        }
        if (tid < 64) vbuf[0][tid] = 1.0f + 0.001f*(float)tid;
        __syncthreads();
        int i = tid >> 2, p4 = tid & 3;
        for (int it = 0; it < 6; ++it) {
            const float* v = vbuf[it & 1];
            float s = 0.f;
            #pragma unroll
            for (int l4 = 0; l4 < 4; ++l4) {
                int lb = p4*16 + l4*4;
                float4 m = *(const float4*)&cur[i*68 + lb];
                s += m.x*v[lb] + m.y*v[lb+1] + m.z*v[lb+2] + m.w*v[lb+3];
            }
            s += __shfl_xor_sync(0xffffffffu, s, 1);
            s += __shfl_xor_sync(0xffffffffu, s, 2);
            if (p4 == 0) vbuf[(it+1)&1][i] = s;
            __syncthreads();
            if (it == 3) {
                float* vn = vbuf[(it+1)&1];
                if (tid < 64) red[tid] = vn[tid]*vn[tid];
                __syncthreads();
                for (int st = 32; st > 0; st >>= 1) {
                    if (tid < st) red[tid] += red[tid+st];
                    __syncthreads();
                }
                float scl = rsqrtf(red[0]);
                if (tid < 64) vn[tid] *= scl;
                __syncthreads();
            }
        }
        const float* vf = vbuf[0];
        float* tvec = oth;
        if (tid < 128) {
            float s = 0.f;
            #pragma unroll 4
            for (int kk = 0; kk < 64; ++kk) s += sW[kk*132 + tid] * vf[kk];
            tvec[tid] = s;
        }
        __syncthreads();
        if (tid < 64) {
            float s = 0.f;
            #pragma unroll 4
            for (int d = 0; d < 128; ++d) s += sW[tid*132 + d] * tvec[d];
            red[tid]  = s * vf[tid];
            red2[tid] = vf[tid]*vf[tid];
        }
        __syncthreads();
        for (int st = 32; st > 0; st >>= 1) {
            if (tid < st) { red[tid] += red[tid+st]; red2[tid] += red2[tid+st]; }
            __syncthreads();
        }
        if (tid == 0) {
            g_sigma_inv = rsqrtf(red[0] / red2[0]);
            __threadfence();
            atomicAdd(&g_sflag, 1);
        }
        return;
    }

    // ------------------------- pipeline blocks ------------------------------
    __shared__ float4 sSum[4*64];
    __shared__ float2 sPre[64];
    __shared__ float  sA0[64];
    __shared__ float  sO0[64];
    __shared__ int    sL;

    int lin = blockIdx.x - 1;         // 0..511
    int p   = lin & (SEQB-1);
    int bt0 = lin * TPB;
    int lane = tid & 31, wid = tid >> 5;

    if (tid == 0) sL = atomicAdd(&g_gen[blockIdx.x], 1) + 1;

    // --- L2 prefetch of this block's alpha/omega slabs (32KB each) so the
    //     epilogue's loads hit L2 instead of cold DRAM; overlaps GEMM. ---
    {
        const char* amb = (const char*)(alpha_mod + (size_t)bt0*64);
        const char* omb = (const char*)(omega_mod + (size_t)bt0*64);
        size_t off = (size_t)tid * 128;     // 256 threads x 128B = 32KB
        asm volatile("prefetch.global.L2 [%0];" :: "l"(amb + off));
        asm volatile("prefetch.global.L2 [%0];" :: "l"(omb + off));
    }

    // --- convert x/W -> bf16 hi/lo planes ---
    char* smc = (char*)sm;
    uint32_t* xhi = (uint32_t*)(smc + XHI_B);   // u32 index = row*68 + d2
    uint32_t* xlo = (uint32_t*)(smc + XLO_B);
    uint32_t* whi = (uint32_t*)(smc + WHI_B);
    uint32_t* wlo = (uint32_t*)(smc + WLO_B);

    const float4* xg4 = (const float4*)x + (size_t)bt0*32;
    #pragma unroll
    for (int r = 0; r < 16; ++r) {
        int l = tid + r*256;
        int row = l >> 5, d4 = l & 31;
        float4 v = xg4[l];
        __nv_bfloat16 hx = __float2bfloat16_rn(v.x), hy = __float2bfloat16_rn(v.y);
        __nv_bfloat16 hz = __float2bfloat16_rn(v.z), hw = __float2bfloat16_rn(v.w);
        uint2 hiq, loq;
        {
            __nv_bfloat162 p0; p0.x = hx; p0.y = hy; hiq.x = *(uint32_t*)&p0;
            __nv_bfloat162 p1; p1.x = hz; p1.y = hw; hiq.y = *(uint32_t*)&p1;
        }
        loq.x = pack_bf2(v.x - __bfloat162float(hx), v.y - __bfloat162float(hy));
        loq.y = pack_bf2(v.z - __bfloat162float(hz), v.w - __bfloat162float(hw));
        *(uint2*)&xhi[row*68 + d4*2] = hiq;
        *(uint2*)&xlo[row*68 + d4*2] = loq;
    }
    const float4* Wg4 = (const float4*)W;
    #pragma unroll
    for (int r = 0; r < 8; ++r) {
        int l = tid + r*256;
        int row = l >> 5, d4 = l & 31;
        float4 v = Wg4[l];
        __nv_bfloat16 hx = __float2bfloat16_rn(v.x), hy = __float2bfloat16_rn(v.y);
        __nv_bfloat16 hz = __float2bfloat16_rn(v.z), hw = __float2bfloat16_rn(v.w);
        uint2 hiq, loq;
        {
            __nv_bfloat162 p0; p0.x = hx; p0.y = hy; hiq.x = *(uint32_t*)&p0;
            __nv_bfloat162 p1; p1.x = hz; p1.y = hw; hiq.y = *(uint32_t*)&p1;
        }
        loq.x = pack_bf2(v.x - __bfloat162float(hx), v.y - __bfloat162float(hy));
        loq.y = pack_bf2(v.z - __bfloat162float(hz), v.w - __bfloat162float(hw));
        *(uint2*)&whi[row*68 + d4*2] = hiq;
        *(uint2*)&wlo[row*68 + d4*2] = loq;
    }
    if (tid < 64) {
        float tauv = softplusf(tau_raw[0]) + 1e-3f;
        sA0[tid] = (softplusf(s_real_raw[tid]) + 1e-6f) * tauv;
        sO0[tid] = s_imag[tid] * tauv;
    }
    __syncthreads();
    int L = sL;

    // --- HMMA GEMM: warp w = rows [w*16, w*16+16), all 64 k, K=128 ---
    uint32_t smb = smem_u32(sm);
    uint32_t aoff = (uint32_t)(((wid*16 + (lane & 15))*136 + (lane >> 4)*8) * 2);
    uint32_t boff = (uint32_t)(((((lane & 7) + ((lane >> 3) & 1)*8))*136 + (lane >> 4)*8) * 2);

    float c[8][4];
    #pragma unroll
    for (int nt = 0; nt < 8; ++nt){
        #pragma unroll
        for (int q = 0; q < 4; ++q) c[nt][q] = 0.f;
    }
    const uint32_t Ab[3] = {XHI_B, XHI_B, XLO_B};
    const uint32_t Bb[3] = {WHI_B, WLO_B, WHI_B};
    #pragma unroll
    for (int ps = 0; ps < 3; ++ps) {
        uint32_t Abase = smb + Ab[ps] + aoff;
        uint32_t Bbase = smb + Bb[ps] + boff;
        #pragma unroll
        for (int ks = 0; ks < 8; ++ks) {
            uint32_t a0,a1,a2,a3;
            LDSM_X4(a0,a1,a2,a3, Abase + ks*32);
            #pragma unroll
            for (int np = 0; np < 4; ++np) {
                uint32_t b0,b1,b2,b3;
                LDSM_X4(b0,b1,b2,b3, Bbase + np*4352 + ks*32);
                MMA_BF16(c[np*2][0],c[np*2][1],c[np*2][2],c[np*2][3],
                         a0,a1,a2,a3, b0,b2);
                MMA_BF16(c[np*2+1][0],c[np*2+1][1],c[np*2+1][2],c[np*2+1][3],
                         a0,a1,a2,a3, b1,b3);
            }
        }
    }
    __syncthreads();   // tiles dead; reuse as staging

    float*    sU   = sm;                        // [128][68] float
    uint32_t* adth = (uint32_t*)(smc + 34816);  // [128][68] u32 (half2)

    // --- store D fragments -> sU (raw u, sigma/bias applied in scans) ---
    {
        int g = wid*16 + (lane >> 2);
        int cb = 2*(lane & 3);
        #pragma unroll
        for (int nt = 0; nt < 8; ++nt) {
            int col = nt*8 + cb;
            *(float2*)&sU[g*68 + col]     = make_float2(c[nt][0], c[nt][1]);
            *(float2*)&sU[(g+8)*68 + col] = make_float2(c[nt][2], c[nt][3]);
        }
    }

    // --- epilogue: (ad,th) -> half2 ---
    int kq = tid & 7, bq = tid >> 3;
    #pragma unroll
    for (int a = 0; a < 4; ++a) {
        int tl = bq*4 + a;
        int bt = bt0 + tl;
        float dtv = dt[bt];
        float tm  = tau_mod[bt];
        #pragma unroll
        for (int j = 0; j < 8; ++j) {
            int k2 = kq + 8*j;
            int idx = bt*64 + k2;
            float ad = sA0[k2] * __expf(alpha_mod[idx] + tm) * dtv;
            float th = sO0[k2] * __expf(omega_mod[idx] + tm) * dtv;
            __half2 hv = __floats2half2_rn(ad, th);
            adth[tl*68 + k2] = *(uint32_t*)&hv;
        }
    }

    // --- wait for sigma (overlapped by GEMM + epilogue) ---
    if (tid == 0) {
        while (atomicAdd(&g_sflag, 0) < L) __nanosleep(100);
    }
    __syncthreads();
    __threadfence();
    float siginv = *(volatile float*)&g_sigma_inv;

    int cc = tid >> 6, k = tid & 63;  // 4 sub-chunks x 64 lanes
    float bk = bvec[k];

    // --- local sub-chunk scans: 4 x 32 steps ---
    {
        int tb = cc*32;
        float zr=0.f, zi=0.f, Ar=1.f, Ai=0.f;
        #pragma unroll 8
        for (int i = 0; i < 32; ++i) {
            uint32_t pk = adth[(tb+i)*68 + k];
            float2 at = __half22float2(*(__half2*)&pk);
            float ad = at.x, th = at.y;
            float rho = 1.f - ad*(1.f - ad*(0.5f - 0.16666667f*ad));
            float t2  = th*th;
            float cs  = 1.f - 0.5f*t2*(1.f - 0.083333336f*t2);
            float sn  = th*(1.f - 0.16666667f*t2);
            float ar = rho*cs, ai = rho*sn;
            float u  = siginv*sU[(tb+i)*68 + k] + bk;
            float nr = ar*zr - ai*zi + u;
            float ni = ai*zr + ar*zi;
            zr = nr; zi = ni;
            float br = ar*Ar - ai*Ai;
            float bi = ai*Ar + ar*Ai;
            Ar = br; Ai = bi;
        }
        sSum[cc*64 + k] = make_float4(Ar, Ai, zr, zi);
    }
    __syncthreads();

    // --- block aggregate (lanes 0..63), publish agg + counter ---
    if (tid < 64) {
        float bAr=1.f, bAi=0.f, bZr=0.f, bZi=0.f;
        #pragma unroll
        for (int j = 0; j < 4; ++j) {
            float4 s4 = sSum[j*64 + tid];
            float nzr = s4.x*bZr - s4.y*bZi + s4.z;
            float nzi = s4.y*bZr + s4.x*bZi + s4.w;
            float nar = s4.x*bAr - s4.y*bAi;
            float nai = s4.y*bAr + s4.x*bAi;
            bZr=nzr; bZi=nzi; bAr=nar; bAi=nai;
        }
        g_agg[lin*Kk + tid] = make_float4(bAr, bAi, bZr, bZi);
        __threadfence();
    }
    __syncthreads();
    if (tid == 0) atomicAdd(&g_bst[lin], 1);

    // --- parallel lookback ---
    float pr = 0.f, pi = 0.f;
    if (p > 0) {
        if (tid < p) {
            while (atomicAdd(&g_bst[lin - 1 - tid], 0) < L) __nanosleep(60);
        }
        __syncthreads();
        __threadfence();
        if (tid < 64) {
            float Ra=1.f, Rb=0.f, Rzr=0.f, Rzi=0.f;
            int w = lin - 1;
            int wend = lin - p;
            while (w >= wend) {
                int nb = w - wend + 1; if (nb > 8) nb = 8;
                float4 ag[8];
                #pragma unroll
                for (int b = 0; b < 8; ++b) {
                    if (b < nb) ag[b] = __ldcg(&g_agg[(w - b)*Kk + tid]);
                }
                #pragma unroll
                for (int b = 0; b < 8; ++b) {
                    if (b < nb) {
                        float4 A = ag[b];
                        float nzr = Ra*A.z - Rb*A.w + Rzr;
                        float nzi = Rb*A.z + Ra*A.w + Rzi;
                        float nar = Ra*A.x - Rb*A.y;
                        float nai = Ra*A.y + Rb*A.x;
                        Rzr=nzr; Rzi=nzi; Ra=nar; Rb=nai;
                    }
                }
                w -= nb;
            }
            pr = Rzr; pi = Rzi;
        }
    }

    if (tid < 64) sPre[tid] = make_float2(pr, pi);
    __syncthreads();

    // --- final scan with correct init, write output ---
    {
        float2 z0 = sPre[k];
        float zr = z0.x, zi = z0.y;
        #pragma unroll
        for (int j = 0; j < 3; ++j) {
            if (j < cc) {
                float4 s4 = sSum[j*64 + k];
                float nr = s4.x*zr - s4.y*zi + s4.z;
                float ni = s4.y*zr + s4.x*zi + s4.w;
                zr = nr; zi = ni;
            }
        }
        int tb = cc*32;
        float* outb = out + (size_t)(bt0 + tb)*128;
        #pragma unroll 8
        for (int i = 0; i < 32; ++i) {
            uint32_t pk = adth[(tb+i)*68 + k];
            float2 at = __half22float2(*(__half2*)&pk);
            float ad = at.x, th = at.y;
            float rho = 1.f - ad*(1.f - ad*(0.5f - 0.16666667f*ad));
            float t2  = th*th;
            float cs  = 1.f - 0.5f*t2*(1.f - 0.083333336f*t2);
            float sn  = th*(1.f - 0.16666667f*t2);
            float ar = rho*cs, ai = rho*sn;
            float u  = siginv*sU[(tb+i)*68 + k] + bk;
            float nr = ar*zr - ai*zi + u;
            float ni = ai*zr + ar*zi;
            zr = nr; zi = ni;
            outb[i*128 + k]      = zr;   // C
            outb[i*128 + 64 + k] = zi;   // S
        }
    }
}

extern "C" void kernel_launch(void* const* d_in, const int* in_sizes, int n_in,
                              void* d_out, int out_size)
{
    const float* x          = (const float*)d_in[0];
    const float* dt         = (const float*)d_in[1];
    const float* alpha_mod  = (const float*)d_in[2];
    const float* omega_mod  = (const float*)d_in[3];
    const float* tau_mod    = (const float*)d_in[4];
    const float* s_real_raw = (const float*)d_in[5];
    const float* s_imag     = (const float*)d_in[6];
    const float* tau_raw    = (const float*)d_in[7];
    const float* W          = (const float*)d_in[8];
    const float* bvec       = (const float*)d_in[9];
    float* out = (float*)d_out;

    cudaFuncSetAttribute(k_fused, cudaFuncAttributeMaxDynamicSharedMemorySize, SMEM_BYTES);

    k_fused<<<NBLK + 1, NTH, SMEM_BYTES>>>(x, dt, alpha_mod, omega_mod, tau_mod,
                                           bvec, W, s_real_raw, s_imag, tau_raw, out);
}

// round 16
// speedup vs baseline: 1.0516x; 1.0219x over previous
#include <cuda_runtime.h>
#include <cuda_bf16.h>
#include <cuda_fp16.h>
#include <math.h>
#include <stdint.h>

#define Tt 8192
#define Kk 64
#define NBLK 512            // pipeline blocks
#define TPB 128             // timesteps per block
#define SEQB 64             // pipeline blocks per sequence
#define NTH 256

// dynamic smem byte offsets (pipeline blocks)
#define XHI_B 0u
#define XLO_B 34816u
#define WHI_B 69632u
#define WLO_B 87040u
#define SMEM_BYTES 104448
// phase 2 (reuse): sU f32[128][68] @0 (34816B), adth u32[128][68] @34816

// ---- device scratch (static; no runtime alloc allowed) ----
// Monotone generation counters (graph-replay-safe, no reset kernel).
__device__ float4 g_aggA[NBLK*Kk];     // per-block (Ar,Ai,Zx_r,Zx_i), [lin][k]
__device__ float2 g_aggB[NBLK*Kk];     // per-block (Zb_r,Zb_i)
__device__ int    g_gen[NBLK+1];
__device__ int    g_bst[NBLK];
__device__ int    g_sflag;
__device__ float  g_sigma_inv;

__device__ __forceinline__ float softplusf(float x){
    return (x > 20.f) ? x : log1pf(expf(x));
}
__device__ __forceinline__ uint32_t smem_u32(const void* p){
    uint32_t a;
    asm("{ .reg .u64 t; cvta.to.shared.u64 t, %1; cvt.u32.u64 %0, t; }" : "=r"(a) : "l"(p));
    return a;
}
__device__ __forceinline__ uint32_t pack_bf2(float lo, float hi){
    uint32_t r;
    asm("cvt.rn.bf16x2.f32 %0, %1, %2;" : "=r"(r) : "f"(hi), "f"(lo));
    return r;
}
#define LDSM_X4(r0,r1,r2,r3,addr) \
    asm volatile("ldmatrix.sync.aligned.m8n8.x4.shared.b16 {%0,%1,%2,%3}, [%4];" \
        : "=r"(r0),"=r"(r1),"=r"(r2),"=r"(r3) : "r"(addr))
#define MMA_BF16(c0,c1,c2,c3,a0,a1,a2,a3,b0,b1) \
    asm volatile("mma.sync.aligned.m16n8k16.row.col.f32.bf16.bf16.f32 " \
        "{%0,%1,%2,%3},{%4,%5,%6,%7},{%8,%9},{%0,%1,%2,%3};" \
        : "+f"(c0),"+f"(c1),"+f"(c2),"+f"(c3) \
        : "r"(a0),"r"(a1),"r"(a2),"r"(a3),"r"(b0),"r"(b1))

// ============================ fused kernel ==================================
__global__ void __launch_bounds__(NTH, 2)
k_fused(const float* __restrict__ x,
        const float* __restrict__ dt,
        const float* __restrict__ alpha_mod,
        const float* __restrict__ omega_mod,
        const float* __restrict__ tau_mod,
        const float* __restrict__ bvec,
        const float* __restrict__ W,
        const float* __restrict__ s_real_raw,
        const float* __restrict__ s_imag,
        const float* __restrict__ tau_raw,
        float* __restrict__ out)
{
    extern __shared__ float sm[];
    int tid = threadIdx.x;   // 256

    if (blockIdx.x == 0) {
        // ------------------------- sigma block ------------------------------
        float* sW = sm;               // 64 x 132
        float* M  = sm + 64*132;      // 64 x 68
        float* H  = sm + 64*132 + 64*68;
        __shared__ float vbuf[2][64];
        __shared__ float red[64];
        __shared__ float red2[64];

        const float4* W4 = (const float4*)W;
        #pragma unroll
        for (int r = 0; r < 8; ++r) {
            int lin = tid + r*256;
            int k = lin >> 5, d4 = lin & 31;
            ((float4*)&sW[k*132])[d4] = W4[lin];
        }
        __syncthreads();

        int ti = tid >> 4, tj = tid & 15;
        {   // Gram: M = W W^T
            float acc[4][4];
            #pragma unroll
            for (int a=0;a<4;a++){
                #pragma unroll
                for (int b2=0;b2<4;b2++) acc[a][b2]=0.f;
            }
            #pragma unroll 4
            for (int d4 = 0; d4 < 32; ++d4) {
                float4 av[4], bv[4];
                #pragma unroll
                for (int a=0;a<4;a++)  av[a] = ((const float4*)&sW[(ti*4+a)*132])[d4];
                #pragma unroll
                for (int b2=0;b2<4;b2++) bv[b2] = ((const float4*)&sW[(tj*4+b2)*132])[d4];
                #pragma unroll
                for (int a=0;a<4;a++){
                    #pragma unroll
                    for (int b2=0;b2<4;b2++){
                        acc[a][b2] += av[a].x*bv[b2].x + av[a].y*bv[b2].y
                                    + av[a].z*bv[b2].z + av[a].w*bv[b2].w;
                    }
                }
            }
            #pragma unroll
            for (int a=0;a<4;a++){
                #pragma unroll
                for (int b2=0;b2<4;b2++)
                    M[(ti*4+a)*68 + (tj*4+b2)] = acc[a][b2];
            }
        }
        __syncthreads();

        float* cur = M; float* oth = H;
        for (int sq = 0; sq < 5; ++sq) {     // G^32
            float acc[4][4];
            #pragma unroll
            for (int a=0;a<4;a++){
                #pragma unroll
                for (int b2=0;b2<4;b2++) acc[a][b2]=0.f;
            }
            #pragma unroll 4
            for (int l = 0; l < 64; ++l) {
                float a0 = cur[(ti*4+0)*68 + l];
                float a1 = cur[(ti*4+1)*68 + l];
                float a2 = cur[(ti*4+2)*68 + l];
                float a3 = cur[(ti*4+3)*68 + l];
                float4 bv = *(const float4*)&cur[l*68 + tj*4];
                acc[0][0]+=a0*bv.x; acc[0][1]+=a0*bv.y; acc[0][2]+=a0*bv.z; acc[0][3]+=a0*bv.w;
                acc[1][0]+=a1*bv.x; acc[1][1]+=a1*bv.y; acc[1][2]+=a1*bv.z; acc[1][3]+=a1*bv.w;
                acc[2][0]+=a2*bv.x; acc[2][1]+=a2*bv.y; acc[2][2]+=a2*bv.z; acc[2][3]+=a2*bv.w;
                acc[3][0]+=a3*bv.x; acc[3][1]+=a3*bv.y; acc[3][2]+=a3*bv.z; acc[3][3]+=a3*bv.w;
            }
            #pragma unroll
            for (int a=0;a<4;a++){
                #pragma unroll
                for (int b2=0;b2<4;b2++)
                    oth[(ti*4+a)*68 + tj*4+b2] = acc[a][b2];
            }
            __syncthreads();
            // normalize by M[0][0] (> 0 for PSD): no reduction needed
            float sc = 1.0f / oth[0];
            #pragma unroll
            for (int r = 0; r < 16; ++r) {
                int lin = tid + r*256;
                oth[(lin>>6)*68 + (lin&63)] *= sc;
            }
            __syncthreads();
            float* t = cur; cur = oth; oth = t;
        }
        if (tid < 64) vbuf[0][tid] = 1.0f + 0.001f*(float)tid;
        __syncthreads();
        int i = tid >> 2, p4 = tid & 3;
        for (int it = 0; it < 6; ++it) {
            const float* v = vbuf[it & 1];
            float s = 0.f;
            #pragma unroll
            for (int l4 = 0; l4 < 4; ++l4) {
                int lb = p4*16 + l4*4;
                float4 m = *(const float4*)&cur[i*68 + lb];
                s += m.x*v[lb] + m.y*v[lb+1] + m.z*v[lb+2] + m.w*v[lb+3];
            }
            s += __shfl_xor_sync(0xffffffffu, s, 1);
            s += __shfl_xor_sync(0xffffffffu, s, 2);
            if (p4 == 0) vbuf[(it+1)&1][i] = s;
            __syncthreads();
            if (it == 3) {
                float* vn = vbuf[(it+1)&1];
                if (tid < 64) red[tid] = vn[tid]*vn[tid];
                __syncthreads();
                for (int st = 32; st > 0; st >>= 1) {
                    if (tid < st) red[tid] += red[tid+st];
                    __syncthreads();
                }
                float scl = rsqrtf(red[0]);
                if (tid < 64) vn[tid] *= scl;
                __syncthreads();
            }
        }
        const float* vf = vbuf[0];
        float* tvec = oth;
        if (tid < 128) {
            float s = 0.f;
            #pragma unroll 4
            for (int kk = 0; kk < 64; ++kk) s += sW[kk*132 + tid] * vf[kk];
            tvec[tid] = s;
        }
        __syncthreads();
        if (tid < 64) {
            float s = 0.f;
            #pragma unroll 4
            for (int d = 0; d < 128; ++d) s += sW[tid*132 + d] * tvec[d];
            red[tid]  = s * vf[tid];
            red2[tid] = vf[tid]*vf[tid];
        }
        __syncthreads();
        for (int st = 32; st > 0; st >>= 1) {
            if (tid < st) { red[tid] += red[tid+st]; red2[tid] += red2[tid+st]; }
            __syncthreads();
        }
        if (tid == 0) {
            g_sigma_inv = rsqrtf(red[0] / red2[0]);
            __threadfence();
            atomicAdd(&g_sflag, 1);
        }
        return;
    }

    // ------------------------- pipeline blocks ------------------------------
    __shared__ float4 sSumA[4*64];    // sub-chunk (A, Zx)
    __shared__ float2 sSumB[4*64];    // sub-chunk Zb
    __shared__ float4 sPreX[64];      // entering prefix (zx, zb) packed: x,y=zx z,w=zb
    __shared__ float  sA0[64];
    __shared__ float  sO0[64];
    __shared__ int    sL;

    int lin = blockIdx.x - 1;         // 0..511
    int p   = lin & (SEQB-1);
    int bt0 = lin * TPB;
    int lane = tid & 31, wid = tid >> 5;

    if (tid == 0) sL = atomicAdd(&g_gen[blockIdx.x], 1) + 1;

    // L2 prefetch of this block's alpha/omega slabs (overlaps GEMM)
    {
        const char* amb = (const char*)(alpha_mod + (size_t)bt0*64);
        const char* omb = (const char*)(omega_mod + (size_t)bt0*64);
        size_t off = (size_t)tid * 128;
        asm volatile("prefetch.global.L2 [%0];" :: "l"(amb + off));
        asm volatile("prefetch.global.L2 [%0];" :: "l"(omb + off));
    }

    // --- convert x/W -> bf16 hi/lo planes ---
    char* smc = (char*)sm;
    uint32_t* xhi = (uint32_t*)(smc + XHI_B);
    uint32_t* xlo = (uint32_t*)(smc + XLO_B);
    uint32_t* whi = (uint32_t*)(smc + WHI_B);
    uint32_t* wlo = (uint32_t*)(smc + WLO_B);

    const float4* xg4 = (const float4*)x + (size_t)bt0*32;
    #pragma unroll
    for (int r = 0; r < 16; ++r) {
        int l = tid + r*256;
        int row = l >> 5, d4 = l & 31;
        float4 v = xg4[l];
        __nv_bfloat16 hx = __float2bfloat16_rn(v.x), hy = __float2bfloat16_rn(v.y);
        __nv_bfloat16 hz = __float2bfloat16_rn(v.z), hw = __float2bfloat16_rn(v.w);
        uint2 hiq, loq;
        {
            __nv_bfloat162 p0; p0.x = hx; p0.y = hy; hiq.x = *(uint32_t*)&p0;
            __nv_bfloat162 p1; p1.x = hz; p1.y = hw; hiq.y = *(uint32_t*)&p1;
        }
        loq.x = pack_bf2(v.x - __bfloat162float(hx), v.y - __bfloat162float(hy));
        loq.y = pack_bf2(v.z - __bfloat162float(hz), v.w - __bfloat162float(hw));
        *(uint2*)&xhi[row*68 + d4*2] = hiq;
        *(uint2*)&xlo[row*68 + d4*2] = loq;
    }
    const float4* Wg4 = (const float4*)W;
    #pragma unroll
    for (int r = 0; r < 8; ++r) {
        int l = tid + r*256;
        int row = l >> 5, d4 = l & 31;
        float4 v = Wg4[l];
        __nv_bfloat16 hx = __float2bfloat16_rn(v.x), hy = __float2bfloat16_rn(v.y);
        __nv_bfloat16 hz = __float2bfloat16_rn(v.z), hw = __float2bfloat16_rn(v.w);
        uint2 hiq, loq;
        {
            __nv_bfloat162 p0; p0.x = hx; p0.y = hy; hiq.x = *(uint32_t*)&p0;
            __nv_bfloat162 p1; p1.x = hz; p1.y = hw; hiq.y = *(uint32_t*)&p1;
        }
        loq.x = pack_bf2(v.x - __bfloat162float(hx), v.y - __bfloat162float(hy));
        loq.y = pack_bf2(v.z - __bfloat162float(hz), v.w - __bfloat162float(hw));
        *(uint2*)&whi[row*68 + d4*2] = hiq;
        *(uint2*)&wlo[row*68 + d4*2] = loq;
    }
    if (tid < 64) {
        float tauv = softplusf(tau_raw[0]) + 1e-3f;
        sA0[tid] = (softplusf(s_real_raw[tid]) + 1e-6f) * tauv;
        sO0[tid] = s_imag[tid] * tauv;
    }
    __syncthreads();
    int L = sL;

    // --- HMMA GEMM ---
    uint32_t smb = smem_u32(sm);
    uint32_t aoff = (uint32_t)(((wid*16 + (lane & 15))*136 + (lane >> 4)*8) * 2);
    uint32_t boff = (uint32_t)(((((lane & 7) + ((lane >> 3) & 1)*8))*136 + (lane >> 4)*8) * 2);

    float c[8][4];
    #pragma unroll
    for (int nt = 0; nt < 8; ++nt){
        #pragma unroll
        for (int q = 0; q < 4; ++q) c[nt][q] = 0.f;
    }
    const uint32_t Ab[3] = {XHI_B, XHI_B, XLO_B};
    const uint32_t Bb[3] = {WHI_B, WLO_B, WHI_B};
    #pragma unroll
    for (int ps = 0; ps < 3; ++ps) {
        uint32_t Abase = smb + Ab[ps] + aoff;
        uint32_t Bbase = smb + Bb[ps] + boff;
        #pragma unroll
        for (int ks = 0; ks < 8; ++ks) {
            uint32_t a0,a1,a2,a3;
            LDSM_X4(a0,a1,a2,a3, Abase + ks*32);
            #pragma unroll
            for (int np = 0; np < 4; ++np) {
                uint32_t b0,b1,b2,b3;
                LDSM_X4(b0,b1,b2,b3, Bbase + np*4352 + ks*32);
                MMA_BF16(c[np*2][0],c[np*2][1],c[np*2][2],c[np*2][3],
                         a0,a1,a2,a3, b0,b2);
                MMA_BF16(c[np*2+1][0],c[np*2+1][1],c[np*2+1][2],c[np*2+1][3],
                         a0,a1,a2,a3, b1,b3);
            }
        }
    }
    __syncthreads();   // tiles dead; reuse as staging

    float*    sU   = sm;                        // [128][68] float (u_raw)
    uint32_t* adth = (uint32_t*)(smc + 34816);  // [128][68] u32 (half2)

    {
        int g = wid*16 + (lane >> 2);
        int cb = 2*(lane & 3);
        #pragma unroll
        for (int nt = 0; nt < 8; ++nt) {
            int col = nt*8 + cb;
            *(float2*)&sU[g*68 + col]     = make_float2(c[nt][0], c[nt][1]);
            *(float2*)&sU[(g+8)*68 + col] = make_float2(c[nt][2], c[nt][3]);
        }
    }

    // --- epilogue: (ad,th) -> half2 ---
    int kq = tid & 7, bq = tid >> 3;
    #pragma unroll
    for (int a = 0; a < 4; ++a) {
        int tl = bq*4 + a;
        int bt = bt0 + tl;
        float dtv = dt[bt];
        float tm  = tau_mod[bt];
        #pragma unroll
        for (int j = 0; j < 8; ++j) {
            int k2 = kq + 8*j;
            int idx = bt*64 + k2;
            float ad = sA0[k2] * __expf(alpha_mod[idx] + tm) * dtv;
            float th = sO0[k2] * __expf(omega_mod[idx] + tm) * dtv;
            __half2 hv = __floats2half2_rn(ad, th);
            adth[tl*68 + k2] = *(uint32_t*)&hv;
        }
    }
    __syncthreads();

    int cc = tid >> 6, k = tid & 63;  // 4 sub-chunks x 64 lanes
    float bk = bvec[k];

    // --- local sub-chunk DUAL scans (zx with u_raw, zb with const b) ---
    // NO sigma dependency: sigma wait is deferred past the lookback.
    {
        int tb = cc*32;
        float zxr=0.f, zxi=0.f, zbr=0.f, zbi=0.f, Ar=1.f, Ai=0.f;
        #pragma unroll 8
        for (int i = 0; i < 32; ++i) {
            uint32_t pk = adth[(tb+i)*68 + k];
            float2 at = __half22float2(*(__half2*)&pk);
            float ad = at.x, th = at.y;
            float rho = 1.f - ad*(1.f - ad*(0.5f - 0.16666667f*ad));
            float t2  = th*th;
            float cs  = 1.f - 0.5f*t2*(1.f - 0.083333336f*t2);
            float sn  = th*(1.f - 0.16666667f*t2);
            float ar = rho*cs, ai = rho*sn;
            float u  = sU[(tb+i)*68 + k];
            float nxr = ar*zxr - ai*zxi + u;
            float nxi = ai*zxr + ar*zxi;
            float nbr = ar*zbr - ai*zbi + bk;
            float nbi = ai*zbr + ar*zbi;
            zxr = nxr; zxi = nxi; zbr = nbr; zbi = nbi;
            float br = ar*Ar - ai*Ai;
            float bi = ai*Ar + ar*Ai;
            Ar = br; Ai = bi;
        }
        sSumA[cc*64 + k] = make_float4(Ar, Ai, zxr, zxi);
        sSumB[cc*64 + k] = make_float2(zbr, zbi);
    }
    __syncthreads();

    // --- block aggregate (lanes 0..63), publish agg + counter ---
    if (tid < 64) {
        float bAr=1.f, bAi=0.f, bZxr=0.f, bZxi=0.f, bZbr=0.f, bZbi=0.f;
        #pragma unroll
        for (int j = 0; j < 4; ++j) {
            float4 sa = sSumA[j*64 + tid];
            float2 sb = sSumB[j*64 + tid];
            float nxr = sa.x*bZxr - sa.y*bZxi + sa.z;
            float nxi = sa.y*bZxr + sa.x*bZxi + sa.w;
            float nbr = sa.x*bZbr - sa.y*bZbi + sb.x;
            float nbi = sa.y*bZbr + sa.x*bZbi + sb.y;
            float nar = sa.x*bAr - sa.y*bAi;
            float nai = sa.y*bAr + sa.x*bAi;
            bZxr=nxr; bZxi=nxi; bZbr=nbr; bZbi=nbi; bAr=nar; bAi=nai;
        }
        g_aggA[lin*Kk + tid] = make_float4(bAr, bAi, bZxr, bZxi);
        g_aggB[lin*Kk + tid] = make_float2(bZbr, bZbi);
        __threadfence();
    }
    __syncthreads();
    if (tid == 0) atomicAdd(&g_bst[lin], 1);

    // --- parallel lookback (dual) ---
    float pxr = 0.f, pxi = 0.f, pbr = 0.f, pbi = 0.f;
    if (p > 0) {
        if (tid < p) {
            while (atomicAdd(&g_bst[lin - 1 - tid], 0) < L) __nanosleep(60);
        }
        __syncthreads();
        __threadfence();
        if (tid < 64) {
            float Ra=1.f, Rb=0.f, Rxr=0.f, Rxi=0.f, Rbr=0.f, Rbi=0.f;
            int w = lin - 1;
            int wend = lin - p;
            while (w >= wend) {
                int nb = w - wend + 1; if (nb > 8) nb = 8;
                float4 agA[8]; float2 agB[8];
                #pragma unroll
                for (int b = 0; b < 8; ++b) {
                    if (b < nb) {
                        agA[b] = __ldcg(&g_aggA[(w - b)*Kk + tid]);
                        agB[b] = __ldcg(&g_aggB[(w - b)*Kk + tid]);
                    }
                }
                #pragma unroll
                for (int b = 0; b < 8; ++b) {
                    if (b < nb) {
                        float4 A = agA[b]; float2 B = agB[b];
                        float nxr = Ra*A.z - Rb*A.w + Rxr;
                        float nxi = Rb*A.z + Ra*A.w + Rxi;
                        float nbr2 = Ra*B.x - Rb*B.y + Rbr;
                        float nbi2 = Rb*B.x + Ra*B.y + Rbi;
                        float nar = Ra*A.x - Rb*A.y;
                        float nai = Ra*A.y + Rb*A.x;
                        Rxr=nxr; Rxi=nxi; Rbr=nbr2; Rbi=nbi2; Ra=nar; Rb=nai;
                    }
                }
                w -= nb;
            }
            pxr = Rxr; pxi = Rxi; pbr = Rbr; pbi = Rbi;
        }
    }

    if (tid < 64) sPreX[tid] = make_float4(pxr, pxi, pbr, pbi);
    __syncthreads();

    // --- sigma wait: deferred to here (block 0 long since done) ---
    if (tid == 0) {
        while (atomicAdd(&g_sflag, 0) < L) __nanosleep(100);
    }
    __syncthreads();
    __threadfence();
    float siginv = *(volatile float*)&g_sigma_inv;

    // --- final dual scan, combine with sigma at output ---
    {
        float4 z0 = sPreX[k];
        float zxr = z0.x, zxi = z0.y, zbr = z0.z, zbi = z0.w;
        #pragma unroll
        for (int j = 0; j < 3; ++j) {
            if (j < cc) {
                float4 sa = sSumA[j*64 + k];
                float2 sb = sSumB[j*64 + k];
                float nxr = sa.x*zxr - sa.y*zxi + sa.z;
                float nxi = sa.y*zxr + sa.x*zxi + sa.w;
                float nbr = sa.x*zbr - sa.y*zbi + sb.x;
                float nbi = sa.y*zbr + sa.x*zbi + sb.y;
                zxr = nxr; zxi = nxi; zbr = nbr; zbi = nbi;
            }
        }
        int tb = cc*32;
        float* outb = out + (size_t)(bt0 + tb)*128;
        #pragma unroll 8
        for (int i = 0; i < 32; ++i) {
            uint32_t pk = adth[(tb+i)*68 + k];
            float2 at = __half22float2(*(__half2*)&pk);
            float ad = at.x, th = at.y;
            float rho = 1.f - ad*(1.f - ad*(0.5f - 0.16666667f*ad));
            float t2  = th*th;
            float cs  = 1.f - 0.5f*t2*(1.f - 0.083333336f*t2);
            float sn  = th*(1.f - 0.16666667f*t2);
            float ar = rho*cs, ai = rho*sn;
            float u  = sU[(tb+i)*68 + k];
            float nxr = ar*zxr - ai*zxi + u;
            float nxi = ai*zxr + ar*zxi;
            float nbr = ar*zbr - ai*zbi + bk;
            float nbi = ai*zbr + ar*zbi;
            zxr = nxr; zxi = nxi; zbr = nbr; zbi = nbi;
            outb[i*128 + k]      = siginv*zxr + zbr;   // C
            outb[i*128 + 64 + k] = siginv*zxi + zbi;   // S
        }
    }
}

extern "C" void kernel_launch(void* const* d_in, const int* in_sizes, int n_in,
                              void* d_out, int out_size)
{
    const float* x          = (const float*)d_in[0];
    const float* dt         = (const float*)d_in[1];
    const float* alpha_mod  = (const float*)d_in[2];
    const float* omega_mod  = (const float*)d_in[3];
    const float* tau_mod    = (const float*)d_in[4];
    const float* s_real_raw = (const float*)d_in[5];
    const float* s_imag     = (const float*)d_in[6];
    const float* tau_raw    = (const float*)d_in[7];
    const float* W          = (const float*)d_in[8];
    const float* bvec       = (const float*)d_in[9];
    float* out = (float*)d_out;

    cudaFuncSetAttribute(k_fused, cudaFuncAttributeMaxDynamicSharedMemorySize, SMEM_BYTES);

    k_fused<<<NBLK + 1, NTH, SMEM_BYTES>>>(x, dt, alpha_mod, omega_mod, tau_mod,
                                           bvec, W, s_real_raw, s_imag, tau_raw, out);
}